// round 16
// baseline (speedup 1.0000x reference)
#include <cuda_runtime.h>
#include <cuda_fp16.h>
#include <stdint.h>
#include <math.h>

// Problem constants
#define Sdim 512
#define Bdim 16
#define Ddim 2048
#define Hdim 4
#define HDdim 512
#define NB 64
#define Mrows 8192
#define HEAD_ELEMS (Sdim * HDdim)            // 262144
#define ACT_ELEMS ((size_t)Mrows * Ddim)     // 16777216
#define W_ELEMS ((size_t)Ddim * Ddim)        // 4194304
#define ACT_BYTES (ACT_ELEMS * 2)
#define W_BYTES (W_ELEMS * 2)
#define HEAD_BYTES ((size_t)HEAD_ELEMS * 2)

// ---------------- scratch (device globals; no allocation allowed) ----------
__device__ __align__(128) char g_Act[3 * ACT_BYTES];
__device__ __align__(128) char g_W[4 * W_BYTES];
__device__ __align__(128) char g_Q1[(size_t)NB * HEAD_BYTES];
__device__ __align__(128) char g_K1[(size_t)NB * HEAD_BYTES];
__device__ __align__(128) char g_Vt[(size_t)NB * HEAD_BYTES];
__device__ __align__(128) char g_P1[(size_t)NB * HEAD_BYTES];
__device__ __align__(128) char g_C1[ACT_BYTES];
__device__ float g_Vh[(size_t)NB * HEAD_ELEMS];
__device__ float g_scores[(size_t)NB * HEAD_ELEMS];
__device__ float g_attn_fb[(size_t)NB * HEAD_ELEMS];

// ---------------- PTX helpers ------------------------------------------------
__device__ __forceinline__ uint32_t smem_u32(const void* p) {
    uint32_t a;
    asm("{ .reg .u64 t; cvta.to.shared.u64 t, %1; cvt.u32.u64 %0, t; }" : "=r"(a) : "l"(p));
    return a;
}
#define MBARRIER_INIT(a, c) \
    asm volatile("mbarrier.init.shared.b64 [%0], %1;" :: "r"((uint32_t)(a)), "r"((uint32_t)(c)) : "memory")
#define MBARRIER_ARRIVE(a) \
    asm volatile("mbarrier.arrive.shared.b64 _, [%0];" :: "r"((uint32_t)(a)) : "memory")
#define MBARRIER_EXPECT_TX(a, bytes) \
    asm volatile("mbarrier.arrive.expect_tx.shared.b64 _, [%0], %1;" \
        :: "r"((uint32_t)(a)), "r"((uint32_t)(bytes)) : "memory")
#define TMA_BULK(dst, src, bytes, mbar) \
    asm volatile("cp.async.bulk.shared::cluster.global.mbarrier::complete_tx::bytes [%0], [%1], %2, [%3];" \
        :: "r"((uint32_t)(dst)), "l"(src), "r"((uint32_t)(bytes)), "r"((uint32_t)(mbar)) : "memory")
#define MBARRIER_WAIT_PARITY(mbar_smem_addr, phase_parity) do { \
    uint32_t _mbar = (uint32_t)(mbar_smem_addr); \
    uint32_t _parity = (uint32_t)(phase_parity); \
    uint32_t _done; \
    asm volatile("{\n\t.reg .pred p;\n\t" \
        "mbarrier.try_wait.parity.acquire.cta.shared::cta.b64 p, [%1], %2;\n\t" \
        "selp.b32 %0, 1, 0, p;\n\t}" : "=r"(_done) : "r"(_mbar), "r"(_parity) : "memory"); \
    if (!_done) { \
        asm volatile("{\n\t.reg .pred P1;\n\t" \
            "WAIT_LOOP_%=:\n\t" \
            "mbarrier.try_wait.parity.acquire.cta.shared::cta.b64 P1, [%0], %1, 0x989680;\n\t" \
            "@P1 bra.uni WAIT_DONE_%=;\n\t" \
            "bra.uni WAIT_LOOP_%=;\n\t" \
            "WAIT_DONE_%=:\n\t}" :: "r"(_mbar), "r"(_parity) : "memory"); \
    } \
} while (0)

__device__ __forceinline__ void ldsm4(uint32_t* r, uint32_t addr) {
    asm volatile("ldmatrix.sync.aligned.m8n8.x4.shared.b16 {%0,%1,%2,%3}, [%4];"
                 : "=r"(r[0]), "=r"(r[1]), "=r"(r[2]), "=r"(r[3]) : "r"(addr));
}
__device__ __forceinline__ void mma_f16(float* c, const uint32_t* a, const uint32_t* b) {
    asm volatile(
        "mma.sync.aligned.m16n8k16.row.col.f32.f16.f16.f32 "
        "{%0,%1,%2,%3}, {%4,%5,%6,%7}, {%8,%9}, {%0,%1,%2,%3};"
        : "+f"(c[0]), "+f"(c[1]), "+f"(c[2]), "+f"(c[3])
        : "r"(a[0]), "r"(a[1]), "r"(a[2]), "r"(a[3]), "r"(b[0]), "r"(b[1]));
}
__device__ __forceinline__ uint32_t pack2(float a, float b) {
    __half2 h; h.x = __float2half(a); h.y = __float2half(b);
    return *(uint32_t*)&h;
}

// ---------------- tiled slab layouts (64 k-cols per chunk) -------------------
// A slab: [mblk][ch][128 rows][128B] = 16KB  ; B slab: [nblk][ch][256 rows][128B] = 32KB
// swizzle: c16' = c16 ^ (row & 7)   (classic SW128; conflict-free ldmatrix)
__device__ __forceinline__ size_t a_tile_off(int row, int col, int nch) {
    int mblk = row >> 7, ar = row & 127, ch = col >> 6;
    int c16 = ((col >> 3) & 7) ^ (ar & 7);
    return ((size_t)(mblk * nch + ch) << 14) + (size_t)(ar * 128 + c16 * 16 + (col & 7) * 2);
}
__device__ __forceinline__ size_t b_tile_off(int row, int col, int nch) {
    int nblk = row >> 8, br = row & 255, ch = col >> 6;
    int c16 = ((col >> 3) & 7) ^ (br & 7);
    return ((size_t)(nblk * nch + ch) << 15) + (size_t)(br * 128 + c16 * 16 + (col & 7) * 2);
}

// ---------------- fp16 GEMM, bulk loads, producer/consumer mbarriers ---------
// Tile 128x256, chunk=64k (A 16KB + B 32KB). 256 threads = 8 warps (2m x 4n),
// warp tile 64x64. 4-stage bulk pipeline, FULL(tx,1)+EMPTY(8) barriers, no
// __syncthreads in mainloop. Cluster launch is load-bearing for cp.async.bulk.
#define STAGE_B 49152
#define NSTAGE 4
#define GEMM_SMEM (128 + NSTAGE * STAGE_B)    // 196736

enum { EP_F32 = 0, EP_HALF = 1, EP_QKV3 = 2 };

struct HArgs {
    const char *aT, *bT;
    size_t bsA, bsB;
    int nch;                   // K/64
    int ldc;
    size_t bsC;
    float* Cf;
    char *Ch, *Ch2;
    float alpha;
    int mode;
};

__global__ __launch_bounds__(256, 1) __cluster_dims__(1, 1, 1)
void hgemm(HArgs g)
{
    extern __shared__ char smraw[];
    const uint32_t sb = smem_u32(smraw);
    const uint32_t mbF = sb;                // 4 full barriers
    const uint32_t mbE = sb + 32;           // 4 empty barriers
    const uint32_t stbase = sb + 128;
    const int tid = threadIdx.x;
    const int lane = tid & 31;
    const int wid = tid >> 5;               // 0..7
    const int wm = wid & 1;                 // 2 m-warps
    const int wn = wid >> 1;                // 4 n-warps
    const int m0 = blockIdx.y * 128;
    const int n0 = blockIdx.x * 256;
    const size_t z = blockIdx.z;
    const int nch = g.nch;

    const char* aT = g.aT + z * g.bsA;
    const char* bT = g.bT + z * g.bsB;

    float acc[4][8][4];
#pragma unroll
    for (int i = 0; i < 4; i++)
#pragma unroll
        for (int j = 0; j < 8; j++)
#pragma unroll
            for (int x = 0; x < 4; x++) acc[i][j][x] = 0.f;

    if (tid == 0) {
#pragma unroll
        for (int s = 0; s < NSTAGE; s++) {
            MBARRIER_INIT(mbF + s * 8, 1);
            MBARRIER_INIT(mbE + s * 8, 8);
        }
    }
    asm volatile("fence.proxy.async.shared::cta;" ::: "memory");
    __syncthreads();

    auto issue = [&](int ch, int st) {
        uint32_t d = stbase + (uint32_t)st * STAGE_B;
        MBARRIER_EXPECT_TX(mbF + st * 8, STAGE_B);
        TMA_BULK(d,         aT + ((size_t)((int)blockIdx.y * nch + ch) << 14), 16384, mbF + st * 8);
        TMA_BULK(d + 16384, bT + ((size_t)((int)blockIdx.x * nch + ch) << 15), 32768, mbF + st * 8);
    };
    if (tid == 0) {
        int pre = (nch < NSTAGE - 1) ? nch : (NSTAGE - 1);
        for (int s = 0; s < pre; s++) issue(s, s);
    }

    const int a_row_base = wm * 64 + (lane & 15);
    const int a_c16half  = (lane >> 4) & 1;
    const int b_row_base = wn * 64 + (lane & 7) + (((lane >> 4) & 1) << 3);
    const int b_c16half  = (lane >> 3) & 1;

    auto compute = [&](int st) {
        const uint32_t aB = stbase + (uint32_t)st * STAGE_B;
        const uint32_t bB = aB + 16384;
#pragma unroll
        for (int ks = 0; ks < 4; ks++) {
            uint32_t af[4][4];
#pragma unroll
            for (int i = 0; i < 4; i++) {
                int row = a_row_base + i * 16;
                int c16 = (ks * 2 + a_c16half) ^ (row & 7);
                ldsm4(af[i], aB + (uint32_t)(row * 128 + c16 * 16));
            }
#pragma unroll
            for (int g2 = 0; g2 < 4; g2++) {
                uint32_t bf[4];
                int row = b_row_base + g2 * 16;
                int c16 = (ks * 2 + b_c16half) ^ (row & 7);
                ldsm4(bf, bB + (uint32_t)(row * 128 + c16 * 16));
#pragma unroll
                for (int i = 0; i < 4; i++)
#pragma unroll
                    for (int jj = 0; jj < 2; jj++)
                        mma_f16(acc[i][g2 * 2 + jj], af[i], bf + jj * 2);
            }
        }
    };

    uint32_t phases = 0;
    uint32_t ephases = 0;
    int st = 0;
    for (int ch = 0; ch < nch; ch++) {
        MBARRIER_WAIT_PARITY(mbF + st * 8, (phases >> st) & 1);
        phases ^= 1u << st;
        if (tid == 0 && ch + NSTAGE - 1 < nch) {
            int sr = st - 1; if (sr < 0) sr += NSTAGE;
            if (ch >= 1) {
                MBARRIER_WAIT_PARITY(mbE + sr * 8, (ephases >> sr) & 1);
                ephases ^= 1u << sr;
            }
            issue(ch + NSTAGE - 1, sr);
        }
        compute(st);
        if (lane == 0) MBARRIER_ARRIVE(mbE + st * 8);
        if (++st == NSTAGE) st = 0;
    }

    // -------- epilogue --------
    const int quad = lane >> 2, tq = lane & 3;
    const float alpha = g.alpha;
#pragma unroll
    for (int i = 0; i < 4; i++) {
#pragma unroll
        for (int jj = 0; jj < 8; jj++) {
            const int r = m0 + wm * 64 + i * 16 + quad;
            const int c = n0 + wn * 64 + jj * 8 + tq * 2;
            const float v0 = acc[i][jj][0] * alpha;
            const float v1 = acc[i][jj][1] * alpha;
            const float v2 = acc[i][jj][2] * alpha;
            const float v3 = acc[i][jj][3] * alpha;
            if (g.mode == EP_F32) {
                float2 a0; a0.x = v0; a0.y = v1;
                float2 a1; a1.x = v2; a1.y = v3;
                *(float2*)(g.Cf + z * g.bsC + (size_t)r * g.ldc + c) = a0;
                *(float2*)(g.Cf + z * g.bsC + (size_t)(r + 8) * g.ldc + c) = a1;
            } else if (g.mode == EP_HALF) {
                size_t f0 = z * (size_t)HEAD_ELEMS + (size_t)r * HDdim + c;
                size_t f1 = f0 + 8 * HDdim;
                *(uint32_t*)(g.Ch + a_tile_off((int)(f0 >> 11), (int)(f0 & 2047), 32)) = pack2(v0, v1);
                *(uint32_t*)(g.Ch + a_tile_off((int)(f1 >> 11), (int)(f1 & 2047), 32)) = pack2(v2, v3);
            } else {  // EP_QKV3
                int s0 = r >> 4, b0 = r & 15, h = c >> 9, d = c & 511;
                int b1 = (r + 8) & 15;
                int gb0 = b0 * Hdim + h, gb1 = b1 * Hdim + h;
                if (z == 0) {
                    *(uint32_t*)(g.Ch + (size_t)gb0 * HEAD_BYTES + a_tile_off(s0, d, 8)) = pack2(v0, v1);
                    *(uint32_t*)(g.Ch + (size_t)gb1 * HEAD_BYTES + a_tile_off(s0, d, 8)) = pack2(v2, v3);
                } else if (z == 1) {
                    *(uint32_t*)(g.Ch2 + (size_t)gb0 * HEAD_BYTES + b_tile_off(s0, d, 8)) = pack2(v0, v1);
                    *(uint32_t*)(g.Ch2 + (size_t)gb1 * HEAD_BYTES + b_tile_off(s0, d, 8)) = pack2(v2, v3);
                } else {
                    float2 a0; a0.x = v0; a0.y = v1;
                    float2 a1; a1.x = v2; a1.y = v3;
                    *(float2*)(g.Cf + (((size_t)gb0 * Sdim + s0) * HDdim + d)) = a0;
                    *(float2*)(g.Cf + (((size_t)gb1 * Sdim + s0) * HDdim + d)) = a1;
                }
            }
        }
    }
}

// ---------------- fp32 -> fp16 tiled A-slabs (q,k,v) -------------------------
__global__ void cvt_acts(const float* __restrict__ q, const float* __restrict__ k,
                         const float* __restrict__ v, char* __restrict__ dst, int n8)
{
    int i = blockIdx.x * blockDim.x + threadIdx.x;
    if (i >= n8) return;
    const int zz = blockIdx.z;
    const float* x = (zz == 0) ? q : (zz == 1) ? k : v;
    size_t flat = (size_t)i * 8;
    float4 a = ((const float4*)(x + flat))[0];
    float4 b = ((const float4*)(x + flat))[1];
    uint4 u;
    u.x = pack2(a.x, a.y); u.y = pack2(a.z, a.w);
    u.z = pack2(b.x, b.y); u.w = pack2(b.z, b.w);
    int row = (int)(flat >> 11), col = (int)(flat & 2047);
    *(uint4*)(dst + (size_t)zz * ACT_BYTES + a_tile_off(row, col, 32)) = u;
}

// ---------------- fp32 -> fp16 tiled B-slabs (weights) -----------------------
__global__ void cvt_weights(const float* __restrict__ w0, const float* __restrict__ w1,
                            const float* __restrict__ w2, const float* __restrict__ w3,
                            char* __restrict__ dst, int n8)
{
    int i = blockIdx.x * blockDim.x + threadIdx.x;
    if (i >= n8) return;
    const int zz = blockIdx.z;
    const float* x = (zz == 0) ? w0 : (zz == 1) ? w1 : (zz == 2) ? w2 : w3;
    size_t flat = (size_t)i * 8;
    float4 a = ((const float4*)(x + flat))[0];
    float4 b = ((const float4*)(x + flat))[1];
    uint4 u;
    u.x = pack2(a.x, a.y); u.y = pack2(a.z, a.w);
    u.z = pack2(b.x, b.y); u.w = pack2(b.z, b.w);
    int row = (int)(flat >> 11), col = (int)(flat & 2047);
    *(uint4*)(dst + (size_t)zz * W_BYTES + b_tile_off(row, col, 32)) = u;
}

// ---------------- V transpose -> tiled B-slabs for PV ------------------------
__global__ void vtrans_kernel(const float* __restrict__ Vh, char* __restrict__ VtT)
{
    __shared__ float tile[64][33];
    const int gb = blockIdx.z;
    const int t0 = blockIdx.x * 64;
    const int d0 = blockIdx.y * 32;
    const int tx = threadIdx.x, ty = threadIdx.y;   // 32 x 8
    const float* src = Vh + (size_t)gb * HEAD_ELEMS;
#pragma unroll
    for (int i = 0; i < 8; i++)
        tile[ty + i * 8][tx] = src[(size_t)(t0 + ty + i * 8) * HDdim + d0 + tx];
    __syncthreads();
    int u = ty * 32 + tx;
    int dl = u & 31, tg = u >> 5;
    int d = d0 + dl, t = t0 + tg * 8;
    uint4 o;
    o.x = pack2(tile[tg * 8 + 0][dl], tile[tg * 8 + 1][dl]);
    o.y = pack2(tile[tg * 8 + 2][dl], tile[tg * 8 + 3][dl]);
    o.z = pack2(tile[tg * 8 + 4][dl], tile[tg * 8 + 5][dl]);
    o.w = pack2(tile[tg * 8 + 6][dl], tile[tg * 8 + 7][dl]);
    *(uint4*)(VtT + (size_t)gb * HEAD_BYTES + b_tile_off(d, t, 8)) = o;
}

// ---------------- softmax: attn fp32 + P tiled A-slabs -----------------------
__global__ void softmax_kernel(const float* __restrict__ scores,
                               float* __restrict__ attn, char* __restrict__ P1)
{
    int gwarp = (blockIdx.x * blockDim.x + threadIdx.x) >> 5;
    int lane  = threadIdx.x & 31;
    if (gwarp >= NB * Sdim) return;
    int gb = gwarp >> 9;       // b*4+h
    int s  = gwarp & 511;
    int b  = gb >> 2;
    int h  = gb & 3;

    const float4* row = (const float4*)(scores + ((size_t)gb * Sdim + s) * Sdim);
    float vals[16];
    float mx = -1e30f;
#pragma unroll
    for (int j = 0; j < 4; j++) {
        float4 v = row[lane * 4 + j];
        vals[j * 4 + 0] = v.x; vals[j * 4 + 1] = v.y;
        vals[j * 4 + 2] = v.z; vals[j * 4 + 3] = v.w;
        mx = fmaxf(mx, fmaxf(fmaxf(v.x, v.y), fmaxf(v.z, v.w)));
    }
#pragma unroll
    for (int o = 16; o > 0; o >>= 1) mx = fmaxf(mx, __shfl_xor_sync(0xffffffffu, mx, o));
    float sum = 0.f;
#pragma unroll
    for (int i = 0; i < 16; i++) {
        vals[i] = expf(vals[i] - mx);
        sum += vals[i];
    }
#pragma unroll
    for (int o = 16; o > 0; o >>= 1) sum += __shfl_xor_sync(0xffffffffu, sum, o);
    float inv = 1.f / sum;

    float4* arow = (float4*)(attn + (((size_t)b * Sdim + s) * Hdim + h) * HDdim);
#pragma unroll
    for (int j = 0; j < 4; j++) {
        float4 p;
        p.x = vals[j * 4 + 0] * inv; p.y = vals[j * 4 + 1] * inv;
        p.z = vals[j * 4 + 2] * inv; p.w = vals[j * 4 + 3] * inv;
        arow[lane * 4 + j] = p;
    }
    char* pbase = P1 + (size_t)gb * HEAD_BYTES;
#pragma unroll
    for (int gq = 0; gq < 2; gq++) {
        int t = lane * 16 + gq * 8;
        uint4 o;
        o.x = pack2(vals[gq * 8 + 0] * inv, vals[gq * 8 + 1] * inv);
        o.y = pack2(vals[gq * 8 + 2] * inv, vals[gq * 8 + 3] * inv);
        o.z = pack2(vals[gq * 8 + 4] * inv, vals[gq * 8 + 5] * inv);
        o.w = pack2(vals[gq * 8 + 6] * inv, vals[gq * 8 + 7] * inv);
        *(uint4*)(pbase + a_tile_off(s, t, 8)) = o;
    }
}

// ---------------- launch -----------------------------------------------------
extern "C" void kernel_launch(void* const* d_in, const int* in_sizes, int n_in,
                              void* d_out, int out_size)
{
    const float* q  = (const float*)d_in[0];
    const float* k  = (const float*)d_in[1];
    const float* v  = (const float*)d_in[2];
    const float* Wq = (const float*)d_in[3];
    const float* Wk = (const float*)d_in[4];
    const float* Wv = (const float*)d_in[5];
    const float* Wo = (const float*)d_in[6];
    float* out = (float*)d_out;

    char *Act, *W, *Q1, *K1, *Vt, *P1, *C1;
    float *Vh, *Sc, *At;
    cudaGetSymbolAddress((void**)&Act, g_Act);
    cudaGetSymbolAddress((void**)&W, g_W);
    cudaGetSymbolAddress((void**)&Q1, g_Q1);
    cudaGetSymbolAddress((void**)&K1, g_K1);
    cudaGetSymbolAddress((void**)&Vt, g_Vt);
    cudaGetSymbolAddress((void**)&P1, g_P1);
    cudaGetSymbolAddress((void**)&C1, g_C1);
    cudaGetSymbolAddress((void**)&Vh, g_Vh);
    cudaGetSymbolAddress((void**)&Sc, g_scores);
    cudaGetSymbolAddress((void**)&At, g_attn_fb);

    const long MAIN_OUT = (long)Mrows * Ddim;
    float* attn_out = ((long)out_size >= 2 * MAIN_OUT) ? (out + MAIN_OUT) : At;

    cudaFuncSetAttribute(hgemm, cudaFuncAttributeMaxDynamicSharedMemorySize, GEMM_SMEM);

    const int nAct8 = (int)(ACT_ELEMS / 8);
    const int nW8   = (int)(W_ELEMS / 8);
    dim3 cblk(256);
    dim3 gWCvt(nW8 / 256, 1, 4);
    dim3 gActCvt(nAct8 / 256, 1, 3);
    dim3 blk(256);

    cvt_weights<<<gWCvt, cblk>>>(Wq, Wk, Wv, Wo, W, nW8);
    cvt_acts<<<gActCvt, cblk>>>(q, k, v, Act, nAct8);

    // fused Q/K/V projection
    {
        HArgs a;
        a.aT = Act; a.bT = W;
        a.bsA = ACT_BYTES; a.bsB = W_BYTES;
        a.nch = 32; a.ldc = Ddim; a.bsC = 0;
        a.Cf = Vh; a.Ch = Q1; a.Ch2 = K1;
        a.alpha = 1.0f; a.mode = EP_QKV3;
        dim3 grid(Ddim / 256, Mrows / 128, 3);
        hgemm<<<grid, blk, GEMM_SMEM>>>(a);
    }
    // V transpose -> tiled
    {
        dim3 tb(32, 8), tg(Sdim / 64, HDdim / 32, NB);
        vtrans_kernel<<<tg, tb>>>(Vh, Vt);
    }
    // scores = Q K^T / sqrt(hd)
    {
        HArgs a;
        a.aT = Q1; a.bT = K1;
        a.bsA = HEAD_BYTES; a.bsB = HEAD_BYTES;
        a.nch = 8; a.ldc = Sdim; a.bsC = HEAD_ELEMS;
        a.Cf = Sc; a.Ch = nullptr; a.Ch2 = nullptr;
        a.alpha = 0.044194173824159223f; a.mode = EP_F32;
        dim3 grid(Sdim / 256, Sdim / 128, NB);
        hgemm<<<grid, blk, GEMM_SMEM>>>(a);
    }
    // softmax -> attn output + P tiled
    softmax_kernel<<<(NB * Sdim * 32) / 256, 256>>>(Sc, attn_out, P1);
    // context = P V^T -> C1 tiled
    {
        HArgs a;
        a.aT = P1; a.bT = Vt;
        a.bsA = HEAD_BYTES; a.bsB = HEAD_BYTES;
        a.nch = 8; a.ldc = HDdim; a.bsC = 0;
        a.Cf = nullptr; a.Ch = C1; a.Ch2 = nullptr;
        a.alpha = 1.0f; a.mode = EP_HALF;
        dim3 grid(HDdim / 256, Sdim / 128, NB);
        hgemm<<<grid, blk, GEMM_SMEM>>>(a);
    }
    // output = C @ Wo^T
    {
        HArgs a;
        a.aT = C1; a.bT = W + 3 * W_BYTES;
        a.bsA = 0; a.bsB = 0;
        a.nch = 32; a.ldc = Ddim; a.bsC = 0;
        a.Cf = out; a.Ch = nullptr; a.Ch2 = nullptr;
        a.alpha = 1.0f; a.mode = EP_F32;
        dim3 grid(Ddim / 256, Mrows / 128, 1);
        hgemm<<<grid, blk, GEMM_SMEM>>>(a);
    }
}

// round 17
// speedup vs baseline: 1.3999x; 1.3999x over previous
#include <cuda_runtime.h>
#include <cuda_fp16.h>
#include <stdint.h>
#include <math.h>

// Problem constants
#define Sdim 512
#define Bdim 16
#define Ddim 2048
#define Hdim 4
#define HDdim 512
#define NB 64
#define Mrows 8192
#define HEAD_ELEMS (Sdim * HDdim)            // 262144
#define ACT_ELEMS ((size_t)Mrows * Ddim)     // 16777216
#define W_ELEMS ((size_t)Ddim * Ddim)        // 4194304
#define ACT_BYTES (ACT_ELEMS * 2)
#define W_BYTES (W_ELEMS * 2)
#define HEAD_BYTES ((size_t)HEAD_ELEMS * 2)

// ---------------- scratch (device globals; no allocation allowed) ----------
__device__ __align__(128) char g_Act[3 * ACT_BYTES];
__device__ __align__(128) char g_W[4 * W_BYTES];
__device__ __align__(128) char g_Q1[(size_t)NB * HEAD_BYTES];
__device__ __align__(128) char g_K1[(size_t)NB * HEAD_BYTES];
__device__ __align__(128) char g_Vt[(size_t)NB * HEAD_BYTES];
__device__ __align__(128) char g_P1[(size_t)NB * HEAD_BYTES];
__device__ __align__(128) char g_C1[ACT_BYTES];
__device__ float g_Vh[(size_t)NB * HEAD_ELEMS];
__device__ float g_scores[(size_t)NB * HEAD_ELEMS];
__device__ float g_attn_fb[(size_t)NB * HEAD_ELEMS];

// ---------------- PTX helpers ------------------------------------------------
__device__ __forceinline__ uint32_t smem_u32(const void* p) {
    uint32_t a;
    asm("{ .reg .u64 t; cvta.to.shared.u64 t, %1; cvt.u32.u64 %0, t; }" : "=r"(a) : "l"(p));
    return a;
}
#define MBARRIER_INIT(a, c) \
    asm volatile("mbarrier.init.shared.b64 [%0], %1;" :: "r"((uint32_t)(a)), "r"((uint32_t)(c)) : "memory")
#define MBARRIER_ARRIVE(a) \
    asm volatile("mbarrier.arrive.shared.b64 _, [%0];" :: "r"((uint32_t)(a)) : "memory")
#define MBARRIER_EXPECT_TX(a, bytes) \
    asm volatile("mbarrier.arrive.expect_tx.shared.b64 _, [%0], %1;" \
        :: "r"((uint32_t)(a)), "r"((uint32_t)(bytes)) : "memory")
#define TMA_BULK(dst, src, bytes, mbar) \
    asm volatile("cp.async.bulk.shared::cluster.global.mbarrier::complete_tx::bytes [%0], [%1], %2, [%3];" \
        :: "r"((uint32_t)(dst)), "l"(src), "r"((uint32_t)(bytes)), "r"((uint32_t)(mbar)) : "memory")
#define MBARRIER_WAIT_PARITY(mbar_smem_addr, phase_parity) do { \
    uint32_t _mbar = (uint32_t)(mbar_smem_addr); \
    uint32_t _parity = (uint32_t)(phase_parity); \
    uint32_t _done; \
    asm volatile("{\n\t.reg .pred p;\n\t" \
        "mbarrier.try_wait.parity.acquire.cta.shared::cta.b64 p, [%1], %2;\n\t" \
        "selp.b32 %0, 1, 0, p;\n\t}" : "=r"(_done) : "r"(_mbar), "r"(_parity) : "memory"); \
    if (!_done) { \
        asm volatile("{\n\t.reg .pred P1;\n\t" \
            "WAIT_LOOP_%=:\n\t" \
            "mbarrier.try_wait.parity.acquire.cta.shared::cta.b64 P1, [%0], %1, 0x989680;\n\t" \
            "@P1 bra.uni WAIT_DONE_%=;\n\t" \
            "bra.uni WAIT_LOOP_%=;\n\t" \
            "WAIT_DONE_%=:\n\t}" :: "r"(_mbar), "r"(_parity) : "memory"); \
    } \
} while (0)

__device__ __forceinline__ void ldsm4(uint32_t* r, uint32_t addr) {
    asm volatile("ldmatrix.sync.aligned.m8n8.x4.shared.b16 {%0,%1,%2,%3}, [%4];"
                 : "=r"(r[0]), "=r"(r[1]), "=r"(r[2]), "=r"(r[3]) : "r"(addr));
}
__device__ __forceinline__ void mma_f16(float* c, const uint32_t* a, const uint32_t* b) {
    asm volatile(
        "mma.sync.aligned.m16n8k16.row.col.f32.f16.f16.f32 "
        "{%0,%1,%2,%3}, {%4,%5,%6,%7}, {%8,%9}, {%0,%1,%2,%3};"
        : "+f"(c[0]), "+f"(c[1]), "+f"(c[2]), "+f"(c[3])
        : "r"(a[0]), "r"(a[1]), "r"(a[2]), "r"(a[3]), "r"(b[0]), "r"(b[1]));
}
__device__ __forceinline__ uint32_t pack2(float a, float b) {
    __half2 h; h.x = __float2half(a); h.y = __float2half(b);
    return *(uint32_t*)&h;
}

// ---------------- tiled slab layouts (R15 geometry: 32 k-cols, 64B rows) -----
// A slab: [mblk][ch][128 rows][4 x 16B swizzled]  (8KB)
// B slab: [nblk][ch][256 rows][4 x 16B swizzled]  (16KB)
// swizzle: c16' = c16 ^ ((row>>1)&3)
__device__ __forceinline__ size_t a_tile_off(int row, int col, int nch) {
    int mblk = row >> 7, ar = row & 127, ch = col >> 5;
    int swz = ((col >> 3) & 3) ^ ((ar >> 1) & 3);
    return ((size_t)(mblk * nch + ch) << 13) + (size_t)(ar * 64 + swz * 16 + (col & 7) * 2);
}
__device__ __forceinline__ size_t b_tile_off(int row, int col, int nch) {
    int nblk = row >> 8, br = row & 255, ch = col >> 5;
    int swz = ((col >> 3) & 3) ^ ((br >> 1) & 3);
    return ((size_t)(nblk * nch + ch) << 14) + (size_t)(br * 64 + swz * 16 + (col & 7) * 2);
}

// ---------------- fp16 GEMM, bulk loads, dedicated producer warp -------------
// Tile 128x256, chunk=32k. 288 threads: warps 0-7 compute (2m x 4n, 64x64 warp
// tiles); warp 8 lane 0 = bulk-copy producer. 6-stage ring, FULL(tx,1) +
// EMPTY(8) barriers, no __syncthreads in mainloop. Cluster launch required.
#define STAGE_B 24576
#define NSTAGE 6
#define GEMM_SMEM (128 + NSTAGE * STAGE_B)    // 147584

enum { EP_F32 = 0, EP_HALF = 1, EP_QKV3 = 2 };

struct HArgs {
    const char *aT, *bT;
    size_t bsA, bsB;
    int nch;                   // K/32
    int ldc;
    size_t bsC;
    float* Cf;
    char *Ch, *Ch2;
    float alpha;
    int mode;
};

__global__ __launch_bounds__(288, 1) __cluster_dims__(1, 1, 1)
void hgemm(HArgs g)
{
    extern __shared__ char smraw[];
    const uint32_t sb = smem_u32(smraw);
    const uint32_t mbF = sb;                // 6 full barriers
    const uint32_t mbE = sb + 48;           // 6 empty barriers
    const uint32_t stbase = sb + 128;
    const int tid = threadIdx.x;
    const int lane = tid & 31;
    const int wid = tid >> 5;               // 0..8
    const int wm = wid & 1;                 // compute warps: 2 m-warps
    const int wn = wid >> 1;                // 4 n-warps
    const int m0 = blockIdx.y * 128;
    const int n0 = blockIdx.x * 256;
    const size_t z = blockIdx.z;
    const int nch = g.nch;

    const char* aT = g.aT + z * g.bsA;
    const char* bT = g.bT + z * g.bsB;

    if (tid == 0) {
#pragma unroll
        for (int s = 0; s < NSTAGE; s++) {
            MBARRIER_INIT(mbF + s * 8, 1);
            MBARRIER_INIT(mbE + s * 8, 8);
        }
    }
    asm volatile("fence.proxy.async.shared::cta;" ::: "memory");
    __syncthreads();

    if (wid == 8) {
        // ---- producer warp ----
        if (lane == 0) {
            uint32_t eph = 0;
            for (int c = 0; c < nch; c++) {
                int s = c % NSTAGE;
                if (c >= NSTAGE) {
                    MBARRIER_WAIT_PARITY(mbE + s * 8, (eph >> s) & 1);
                    eph ^= 1u << s;
                }
                uint32_t d = stbase + (uint32_t)s * STAGE_B;
                MBARRIER_EXPECT_TX(mbF + s * 8, STAGE_B);
                TMA_BULK(d,        aT + ((size_t)((int)blockIdx.y * nch + c) << 13), 8192,  mbF + s * 8);
                TMA_BULK(d + 8192, bT + ((size_t)((int)blockIdx.x * nch + c) << 14), 16384, mbF + s * 8);
            }
        }
        return;   // producer warp exits; epilogue is compute-warp-only
    }

    // ---- compute warps (0..7) ----
    float acc[4][8][4];
#pragma unroll
    for (int i = 0; i < 4; i++)
#pragma unroll
        for (int j = 0; j < 8; j++)
#pragma unroll
            for (int x = 0; x < 4; x++) acc[i][j][x] = 0.f;

    const int a_row_base = wm * 64 + (lane & 15);
    const int a_c16half  = (lane >> 4) & 1;
    const int b_row_base = wn * 64 + (lane & 7) + (((lane >> 4) & 1) << 3);
    const int b_c16half  = (lane >> 3) & 1;

    auto compute = [&](int st) {
        const uint32_t aB = stbase + (uint32_t)st * STAGE_B;
        const uint32_t bB = aB + 8192;
#pragma unroll
        for (int ks = 0; ks < 2; ks++) {
            uint32_t af[4][4];
#pragma unroll
            for (int i = 0; i < 4; i++) {
                int row = a_row_base + i * 16;
                int c16 = (ks * 2 + a_c16half) ^ ((row >> 1) & 3);
                ldsm4(af[i], aB + (uint32_t)(row * 64 + c16 * 16));
            }
#pragma unroll
            for (int g2 = 0; g2 < 4; g2++) {
                uint32_t bf[4];
                int row = b_row_base + g2 * 16;
                int c16 = (ks * 2 + b_c16half) ^ ((row >> 1) & 3);
                ldsm4(bf, bB + (uint32_t)(row * 64 + c16 * 16));
#pragma unroll
                for (int i = 0; i < 4; i++)
#pragma unroll
                    for (int jj = 0; jj < 2; jj++)
                        mma_f16(acc[i][g2 * 2 + jj], af[i], bf + jj * 2);
            }
        }
    };

    uint32_t phases = 0;
    int st = 0;
    for (int ch = 0; ch < nch; ch++) {
        MBARRIER_WAIT_PARITY(mbF + st * 8, (phases >> st) & 1);
        phases ^= 1u << st;
        compute(st);
        if (lane == 0) MBARRIER_ARRIVE(mbE + st * 8);
        if (++st == NSTAGE) st = 0;
    }

    // -------- epilogue --------
    const int quad = lane >> 2, tq = lane & 3;
    const float alpha = g.alpha;
#pragma unroll
    for (int i = 0; i < 4; i++) {
#pragma unroll
        for (int jj = 0; jj < 8; jj++) {
            const int r = m0 + wm * 64 + i * 16 + quad;
            const int c = n0 + wn * 64 + jj * 8 + tq * 2;
            const float v0 = acc[i][jj][0] * alpha;
            const float v1 = acc[i][jj][1] * alpha;
            const float v2 = acc[i][jj][2] * alpha;
            const float v3 = acc[i][jj][3] * alpha;
            if (g.mode == EP_F32) {
                float2 a0; a0.x = v0; a0.y = v1;
                float2 a1; a1.x = v2; a1.y = v3;
                *(float2*)(g.Cf + z * g.bsC + (size_t)r * g.ldc + c) = a0;
                *(float2*)(g.Cf + z * g.bsC + (size_t)(r + 8) * g.ldc + c) = a1;
            } else if (g.mode == EP_HALF) {
                size_t f0 = z * (size_t)HEAD_ELEMS + (size_t)r * HDdim + c;
                size_t f1 = f0 + 8 * HDdim;
                *(uint32_t*)(g.Ch + a_tile_off((int)(f0 >> 11), (int)(f0 & 2047), 64)) = pack2(v0, v1);
                *(uint32_t*)(g.Ch + a_tile_off((int)(f1 >> 11), (int)(f1 & 2047), 64)) = pack2(v2, v3);
            } else {  // EP_QKV3
                int s0 = r >> 4, b0 = r & 15, h = c >> 9, d = c & 511;
                int b1 = (r + 8) & 15;
                int gb0 = b0 * Hdim + h, gb1 = b1 * Hdim + h;
                if (z == 0) {
                    *(uint32_t*)(g.Ch + (size_t)gb0 * HEAD_BYTES + a_tile_off(s0, d, 16)) = pack2(v0, v1);
                    *(uint32_t*)(g.Ch + (size_t)gb1 * HEAD_BYTES + a_tile_off(s0, d, 16)) = pack2(v2, v3);
                } else if (z == 1) {
                    *(uint32_t*)(g.Ch2 + (size_t)gb0 * HEAD_BYTES + b_tile_off(s0, d, 16)) = pack2(v0, v1);
                    *(uint32_t*)(g.Ch2 + (size_t)gb1 * HEAD_BYTES + b_tile_off(s0, d, 16)) = pack2(v2, v3);
                } else {
                    float2 a0; a0.x = v0; a0.y = v1;
                    float2 a1; a1.x = v2; a1.y = v3;
                    *(float2*)(g.Cf + (((size_t)gb0 * Sdim + s0) * HDdim + d)) = a0;
                    *(float2*)(g.Cf + (((size_t)gb1 * Sdim + s0) * HDdim + d)) = a1;
                }
            }
        }
    }
}

// ---------------- fp32 -> fp16 tiled A-slabs (q,k,v) -------------------------
__global__ void cvt_acts(const float* __restrict__ q, const float* __restrict__ k,
                         const float* __restrict__ v, char* __restrict__ dst, int n8)
{
    int i = blockIdx.x * blockDim.x + threadIdx.x;
    if (i >= n8) return;
    const int zz = blockIdx.z;
    const float* x = (zz == 0) ? q : (zz == 1) ? k : v;
    size_t flat = (size_t)i * 8;
    float4 a = ((const float4*)(x + flat))[0];
    float4 b = ((const float4*)(x + flat))[1];
    uint4 u;
    u.x = pack2(a.x, a.y); u.y = pack2(a.z, a.w);
    u.z = pack2(b.x, b.y); u.w = pack2(b.z, b.w);
    int row = (int)(flat >> 11), col = (int)(flat & 2047);
    int mblk = row >> 7, ar = row & 127, ch = col >> 5;
    int swz = ((col >> 3) & 3) ^ ((ar >> 1) & 3);
    size_t off = ((size_t)(mblk * 64 + ch) << 13) + (size_t)(ar * 64 + swz * 16);
    *(uint4*)(dst + (size_t)zz * ACT_BYTES + off) = u;
}

// ---------------- fp32 -> fp16 tiled B-slabs (weights) -----------------------
__global__ void cvt_weights(const float* __restrict__ w0, const float* __restrict__ w1,
                            const float* __restrict__ w2, const float* __restrict__ w3,
                            char* __restrict__ dst, int n8)
{
    int i = blockIdx.x * blockDim.x + threadIdx.x;
    if (i >= n8) return;
    const int zz = blockIdx.z;
    const float* x = (zz == 0) ? w0 : (zz == 1) ? w1 : (zz == 2) ? w2 : w3;
    size_t flat = (size_t)i * 8;
    float4 a = ((const float4*)(x + flat))[0];
    float4 b = ((const float4*)(x + flat))[1];
    uint4 u;
    u.x = pack2(a.x, a.y); u.y = pack2(a.z, a.w);
    u.z = pack2(b.x, b.y); u.w = pack2(b.z, b.w);
    int row = (int)(flat >> 11), col = (int)(flat & 2047);
    int nblk = row >> 8, br = row & 255, ch = col >> 5;
    int swz = ((col >> 3) & 3) ^ ((br >> 1) & 3);
    size_t off = ((size_t)(nblk * 64 + ch) << 14) + (size_t)(br * 64 + swz * 16);
    *(uint4*)(dst + (size_t)zz * W_BYTES + off) = u;
}

// ---------------- V transpose -> tiled B-slabs for PV ------------------------
__global__ void vtrans_kernel(const float* __restrict__ Vh, char* __restrict__ VtT)
{
    __shared__ float tile[64][33];
    const int gb = blockIdx.z;
    const int t0 = blockIdx.x * 64;
    const int d0 = blockIdx.y * 32;
    const int tx = threadIdx.x, ty = threadIdx.y;   // 32 x 8
    const float* src = Vh + (size_t)gb * HEAD_ELEMS;
#pragma unroll
    for (int i = 0; i < 8; i++)
        tile[ty + i * 8][tx] = src[(size_t)(t0 + ty + i * 8) * HDdim + d0 + tx];
    __syncthreads();
    int u = ty * 32 + tx;
    int dl = u & 31, tg = u >> 5;
    int d = d0 + dl, t = t0 + tg * 8;
    uint4 o;
    o.x = pack2(tile[tg * 8 + 0][dl], tile[tg * 8 + 1][dl]);
    o.y = pack2(tile[tg * 8 + 2][dl], tile[tg * 8 + 3][dl]);
    o.z = pack2(tile[tg * 8 + 4][dl], tile[tg * 8 + 5][dl]);
    o.w = pack2(tile[tg * 8 + 6][dl], tile[tg * 8 + 7][dl]);
    *(uint4*)(VtT + (size_t)gb * HEAD_BYTES + b_tile_off(d, t, 16)) = o;
}

// ---------------- softmax: attn fp32 + P tiled A-slabs -----------------------
__global__ void softmax_kernel(const float* __restrict__ scores,
                               float* __restrict__ attn, char* __restrict__ P1)
{
    int gwarp = (blockIdx.x * blockDim.x + threadIdx.x) >> 5;
    int lane  = threadIdx.x & 31;
    if (gwarp >= NB * Sdim) return;
    int gb = gwarp >> 9;       // b*4+h
    int s  = gwarp & 511;
    int b  = gb >> 2;
    int h  = gb & 3;

    const float4* row = (const float4*)(scores + ((size_t)gb * Sdim + s) * Sdim);
    float vals[16];
    float mx = -1e30f;
#pragma unroll
    for (int j = 0; j < 4; j++) {
        float4 v = row[lane * 4 + j];
        vals[j * 4 + 0] = v.x; vals[j * 4 + 1] = v.y;
        vals[j * 4 + 2] = v.z; vals[j * 4 + 3] = v.w;
        mx = fmaxf(mx, fmaxf(fmaxf(v.x, v.y), fmaxf(v.z, v.w)));
    }
#pragma unroll
    for (int o = 16; o > 0; o >>= 1) mx = fmaxf(mx, __shfl_xor_sync(0xffffffffu, mx, o));
    float sum = 0.f;
#pragma unroll
    for (int i = 0; i < 16; i++) {
        vals[i] = expf(vals[i] - mx);
        sum += vals[i];
    }
#pragma unroll
    for (int o = 16; o > 0; o >>= 1) sum += __shfl_xor_sync(0xffffffffu, sum, o);
    float inv = 1.f / sum;

    float4* arow = (float4*)(attn + (((size_t)b * Sdim + s) * Hdim + h) * HDdim);
#pragma unroll
    for (int j = 0; j < 4; j++) {
        float4 p;
        p.x = vals[j * 4 + 0] * inv; p.y = vals[j * 4 + 1] * inv;
        p.z = vals[j * 4 + 2] * inv; p.w = vals[j * 4 + 3] * inv;
        arow[lane * 4 + j] = p;
    }
    char* pbase = P1 + (size_t)gb * HEAD_BYTES;
#pragma unroll
    for (int gq = 0; gq < 2; gq++) {
        int t = lane * 16 + gq * 8;
        uint4 o;
        o.x = pack2(vals[gq * 8 + 0] * inv, vals[gq * 8 + 1] * inv);
        o.y = pack2(vals[gq * 8 + 2] * inv, vals[gq * 8 + 3] * inv);
        o.z = pack2(vals[gq * 8 + 4] * inv, vals[gq * 8 + 5] * inv);
        o.w = pack2(vals[gq * 8 + 6] * inv, vals[gq * 8 + 7] * inv);
        *(uint4*)(pbase + a_tile_off(s, t, 16)) = o;
    }
}

// ---------------- launch -----------------------------------------------------
extern "C" void kernel_launch(void* const* d_in, const int* in_sizes, int n_in,
                              void* d_out, int out_size)
{
    const float* q  = (const float*)d_in[0];
    const float* k  = (const float*)d_in[1];
    const float* v  = (const float*)d_in[2];
    const float* Wq = (const float*)d_in[3];
    const float* Wk = (const float*)d_in[4];
    const float* Wv = (const float*)d_in[5];
    const float* Wo = (const float*)d_in[6];
    float* out = (float*)d_out;

    char *Act, *W, *Q1, *K1, *Vt, *P1, *C1;
    float *Vh, *Sc, *At;
    cudaGetSymbolAddress((void**)&Act, g_Act);
    cudaGetSymbolAddress((void**)&W, g_W);
    cudaGetSymbolAddress((void**)&Q1, g_Q1);
    cudaGetSymbolAddress((void**)&K1, g_K1);
    cudaGetSymbolAddress((void**)&Vt, g_Vt);
    cudaGetSymbolAddress((void**)&P1, g_P1);
    cudaGetSymbolAddress((void**)&C1, g_C1);
    cudaGetSymbolAddress((void**)&Vh, g_Vh);
    cudaGetSymbolAddress((void**)&Sc, g_scores);
    cudaGetSymbolAddress((void**)&At, g_attn_fb);

    const long MAIN_OUT = (long)Mrows * Ddim;
    float* attn_out = ((long)out_size >= 2 * MAIN_OUT) ? (out + MAIN_OUT) : At;

    cudaFuncSetAttribute(hgemm, cudaFuncAttributeMaxDynamicSharedMemorySize, GEMM_SMEM);

    const int nAct8 = (int)(ACT_ELEMS / 8);
    const int nW8   = (int)(W_ELEMS / 8);
    dim3 cblk(256);
    dim3 gWCvt(nW8 / 256, 1, 4);
    dim3 gActCvt(nAct8 / 256, 1, 3);
    dim3 blk(288);

    cvt_weights<<<gWCvt, cblk>>>(Wq, Wk, Wv, Wo, W, nW8);
    cvt_acts<<<gActCvt, cblk>>>(q, k, v, Act, nAct8);

    // fused Q/K/V projection
    {
        HArgs a;
        a.aT = Act; a.bT = W;
        a.bsA = ACT_BYTES; a.bsB = W_BYTES;
        a.nch = 64; a.ldc = Ddim; a.bsC = 0;
        a.Cf = Vh; a.Ch = Q1; a.Ch2 = K1;
        a.alpha = 1.0f; a.mode = EP_QKV3;
        dim3 grid(Ddim / 256, Mrows / 128, 3);
        hgemm<<<grid, blk, GEMM_SMEM>>>(a);
    }
    // V transpose -> tiled
    {
        dim3 tb(32, 8), tg(Sdim / 64, HDdim / 32, NB);
        vtrans_kernel<<<tg, tb>>>(Vh, Vt);
    }
    // scores = Q K^T / sqrt(hd)
    {
        HArgs a;
        a.aT = Q1; a.bT = K1;
        a.bsA = HEAD_BYTES; a.bsB = HEAD_BYTES;
        a.nch = 16; a.ldc = Sdim; a.bsC = HEAD_ELEMS;
        a.Cf = Sc; a.Ch = nullptr; a.Ch2 = nullptr;
        a.alpha = 0.044194173824159223f; a.mode = EP_F32;
        dim3 grid(Sdim / 256, Sdim / 128, NB);
        hgemm<<<grid, blk, GEMM_SMEM>>>(a);
    }
    // softmax -> attn output + P tiled
    softmax_kernel<<<(NB * Sdim * 32) / 256, 256>>>(Sc, attn_out, P1);
    // context = P V^T -> C1 tiled
    {
        HArgs a;
        a.aT = P1; a.bT = Vt;
        a.bsA = HEAD_BYTES; a.bsB = HEAD_BYTES;
        a.nch = 16; a.ldc = HDdim; a.bsC = 0;
        a.Cf = nullptr; a.Ch = C1; a.Ch2 = nullptr;
        a.alpha = 1.0f; a.mode = EP_HALF;
        dim3 grid(HDdim / 256, Sdim / 128, NB);
        hgemm<<<grid, blk, GEMM_SMEM>>>(a);
    }
    // output = C @ Wo^T
    {
        HArgs a;
        a.aT = C1; a.bT = W + 3 * W_BYTES;
        a.bsA = 0; a.bsB = 0;
        a.nch = 64; a.ldc = Ddim; a.bsC = 0;
        a.Cf = out; a.Ch = nullptr; a.Ch2 = nullptr;
        a.alpha = 1.0f; a.mode = EP_F32;
        dim3 grid(Ddim / 256, Mrows / 128, 1);
        hgemm<<<grid, blk, GEMM_SMEM>>>(a);
    }
}